// round 15
// baseline (speedup 1.0000x reference)
#include <cuda_runtime.h>
#include <cuda_fp16.h>
#include <math.h>
#include <stdint.h>

#define Bsz 4
#define Nn 1024
#define IND 128
#define Dd 512
#define Hh 8
#define HDd 64
#define Ee 4
#define Ll 3
#define BNROWS (Bsz*Nn)   // 4096

// ---------------------------------------------------------------------------
// Scratch (device globals: no cudaMalloc allowed)
// ---------------------------------------------------------------------------
__device__ float  g_h   [BNROWS*Dd];
__device__ __half g_h16 [BNROWS*Dd];
__device__ __half g_x16 [BNROWS*IND];
__device__ __half g_q16 [BNROWS*Dd];
__device__ __half g_k16 [BNROWS*Dd];
__device__ __half g_v16 [BNROWS*Dd];
__device__ __half g_ao16[BNROWS*Dd];
// transposed fp16 weights: in_w^T [512][128], then per (l, {q,k,v,o}): [512][512]
__device__ __half g_w16t[512*128 + 12*512*512];
// per-layer edge bias: [L][B][H][N][N] fp16
__device__ __half g_bias16[(size_t)Ll*Bsz*Hh*Nn*Nn];

#define WOFF_L(l, m) (512*128 + ((size_t)((l)*4 + (m)))*512*512)

// ---------------------------------------------------------------------------
// helpers
// ---------------------------------------------------------------------------
__device__ __forceinline__ uint32_t pk(float x, float y) {
    __half2 h = __floats2half2_rn(x, y);
    return *reinterpret_cast<uint32_t*>(&h);
}

__device__ __forceinline__ uint32_t smem_u32(const void* p) {
    uint32_t a;
    asm("{ .reg .u64 t; cvta.to.shared.u64 t, %1; cvt.u32.u64 %0, t; }"
        : "=r"(a) : "l"(p));
    return a;
}

__device__ __forceinline__ void mma16(float* c, uint32_t a0, uint32_t a1,
                                      uint32_t a2, uint32_t a3,
                                      uint32_t b0, uint32_t b1) {
    asm volatile(
        "mma.sync.aligned.m16n8k16.row.col.f32.f16.f16.f32 "
        "{%0,%1,%2,%3},{%4,%5,%6,%7},{%8,%9},{%0,%1,%2,%3};"
        : "+f"(c[0]), "+f"(c[1]), "+f"(c[2]), "+f"(c[3])
        : "r"(a0), "r"(a1), "r"(a2), "r"(a3), "r"(b0), "r"(b1));
}

#define LDMX4(r0,r1,r2,r3,addr) \
    asm volatile("ldmatrix.sync.aligned.m8n8.x4.shared.b16 {%0,%1,%2,%3}, [%4];" \
                 : "=r"(r0),"=r"(r1),"=r"(r2),"=r"(r3) : "r"(addr))
#define LDMX4T(r0,r1,r2,r3,addr) \
    asm volatile("ldmatrix.sync.aligned.m8n8.x4.trans.shared.b16 {%0,%1,%2,%3}, [%4];" \
                 : "=r"(r0),"=r"(r1),"=r"(r2),"=r"(r3) : "r"(addr))

__device__ __forceinline__ void cpa16(uint32_t dst, const void* src) {
    asm volatile("cp.async.cg.shared.global [%0], [%1], 16;" :: "r"(dst), "l"(src));
}
#define CPA_COMMIT() asm volatile("cp.async.commit_group;")
#define CPA_WAIT1()  asm volatile("cp.async.wait_group 1;")
#define CPA_WAIT0()  asm volatile("cp.async.wait_group 0;")

// ---------------------------------------------------------------------------
// Pre-pass 1: weight convert + transpose -> fp16 [n][k]
// ---------------------------------------------------------------------------
__global__ void wtrans(const float* __restrict__ in_w, const float* __restrict__ qw,
                       const float* __restrict__ kw, const float* __restrict__ vw,
                       const float* __restrict__ ow, __half* __restrict__ w16t) {
    const int z = blockIdx.z;
    const float* src; int K; size_t doff;
    if (z == 0) { src = in_w; K = IND; doff = 0; }
    else {
        const int li = (z - 1) >> 2, m = (z - 1) & 3;
        const float* base = (m == 0) ? qw : (m == 1) ? kw : (m == 2) ? vw : ow;
        src = base + (size_t)li * Dd * Dd;
        K = Dd; doff = 512*128 + (size_t)(z - 1) * 512 * 512;
    }
    const int k0 = blockIdx.x * 32, n0 = blockIdx.y * 32;
    if (k0 >= K) return;
    __shared__ float tile[32][33];
    const int tx = threadIdx.x, ty = threadIdx.y;
    #pragma unroll
    for (int i = 0; i < 4; i++)
        tile[ty + i*8][tx] = src[(size_t)(k0 + ty + i*8) * Dd + n0 + tx];
    __syncthreads();
    #pragma unroll
    for (int i = 0; i < 4; i++)
        w16t[doff + (size_t)(n0 + ty + i*8) * K + k0 + tx] =
            __float2half(tile[tx][ty + i*8]);
}

// Pre-pass 2: x -> fp16
__global__ void cvt_x16(const float* __restrict__ x, __half* __restrict__ x16) {
    const int i = (blockIdx.x * 256 + threadIdx.x) * 8;
    float4 a = *(const float4*)(x + i);
    float4 b = *(const float4*)(x + i + 4);
    uint4 u;
    u.x = pk(a.x, a.y); u.y = pk(a.z, a.w);
    u.z = pk(b.x, b.y); u.w = pk(b.z, b.w);
    *(uint4*)(x16 + i) = u;
}

// Pre-pass 3 (per layer, side stream): edge bias for ONE layer (fp16).
__global__ void edgeproj1(const float* __restrict__ edges, const float* __restrict__ ew,
                          const float* __restrict__ eb, __half* __restrict__ bias16,
                          int l) {
    const int t  = blockIdx.x * 256 + threadIdx.x;   // 524288 threads
    const int jo = t & 127;
    const int i  = (t >> 7) & 1023;
    const int b  = t >> 17;
    const float* ep = edges + (((size_t)b * Nn + i) * Nn + (size_t)jo * 8) * Ee;
    float e[8][4];
    #pragma unroll
    for (int p = 0; p < 8; p++) {
        float4 v = *(const float4*)(ep + p * 4);
        e[p][0] = v.x; e[p][1] = v.y; e[p][2] = v.z; e[p][3] = v.w;
    }
    #pragma unroll
    for (int h = 0; h < Hh; h++) {
        const float w0 = ew[l*32 + h],      w1 = ew[l*32 + 8 + h];
        const float w2 = ew[l*32 + 16 + h], w3 = ew[l*32 + 24 + h];
        const float bb = eb[l*8 + h];
        float v[8];
        #pragma unroll
        for (int p = 0; p < 8; p++)
            v[p] = fmaf(e[p][0],w0, fmaf(e[p][1],w1, fmaf(e[p][2],w2,
                         fmaf(e[p][3],w3, bb))));
        uint4 u;
        u.x = pk(v[0],v[1]); u.y = pk(v[2],v[3]);
        u.z = pk(v[4],v[5]); u.w = pk(v[6],v[7]);
        *(uint4*)(bias16 + (((size_t)((l*Bsz + b)*Hh + h)) << 20)
                          + (size_t)i * Nn + jo * 8) = u;
    }
}

// ---------------------------------------------------------------------------
// fp16 GEMM: C[M x 512] = A16[M x K] @ W16T^T + bias (+ res)
// CTA 128x64, BK=32, 3-stage cp.async, ldmatrix fragments.
// Final tile drains with wait_group 0 (R10 race fix).
// ---------------------------------------------------------------------------
#define GASTR 40
#define GA_HSZ (128*GASTR)        // 5120 halfs
#define GB_HSZ (64*GASTR)         // 2560 halfs
#define GSTG_H (GA_HSZ + GB_HSZ)  // 7680 halfs / stage
#define GEMM_SMEM (3*GSTG_H*2)    // 46080 B

template<bool RES, bool WF32>
__device__ __forceinline__
void gemm16_body(const __half* __restrict__ A16, const __half* __restrict__ WT,
                 const float* __restrict__ bias, const float* __restrict__ res,
                 float* __restrict__ C32, __half* __restrict__ C16,
                 float scale, int K, int bm, int bn) {
    extern __shared__ __half smh[];
    const uint32_t sb = smem_u32(smh);
    const int tid  = threadIdx.x;
    const int lane = tid & 31;
    const int warp = tid >> 5;
    const int wm   = warp & 3;
    const int wn   = warp >> 2;
    const int g    = lane >> 2;
    const int tg   = lane & 3;

    auto issue = [&](int t) {
        const int k0 = t << 5;
        const uint32_t ab = sb + ((t % 3) * GSTG_H) * 2;
        const uint32_t bb = ab + GA_HSZ * 2;
        #pragma unroll
        for (int c = tid; c < 512; c += 256) {
            const int row = c >> 2, cc = c & 3;
            cpa16(ab + (row*GASTR + cc*8)*2,
                  A16 + (size_t)(bm + row)*K + k0 + cc*8);
        }
        { const int row = tid >> 2, cc = tid & 3;
          cpa16(bb + (row*GASTR + cc*8)*2,
                WT + (size_t)(bn + row)*K + k0 + cc*8); }
        CPA_COMMIT();
    };

    float acc[2][4][4];
    #pragma unroll
    for (int mt = 0; mt < 2; mt++)
        #pragma unroll
        for (int nt = 0; nt < 4; nt++)
            #pragma unroll
            for (int e = 0; e < 4; e++) acc[mt][nt][e] = 0.f;

    const int T = K >> 5;
    issue(0); issue(1);

    for (int t = 0; t < T; t++) {
        if (t + 1 < T) { CPA_WAIT1(); } else { CPA_WAIT0(); }
        __syncthreads();
        if (t + 2 < T) issue(t + 2);

        const uint32_t ab = sb + ((t % 3) * GSTG_H) * 2;
        const uint32_t bb = ab + GA_HSZ * 2;
        #pragma unroll
        for (int ks = 0; ks < 2; ks++) {
            uint32_t a[2][4];
            #pragma unroll
            for (int mt = 0; mt < 2; mt++) {
                const uint32_t ad = ab +
                    ((wm*32 + mt*16 + (lane & 15))*GASTR + ks*16 + (lane >> 4)*8)*2;
                LDMX4(a[mt][0], a[mt][1], a[mt][2], a[mt][3], ad);
            }
            uint32_t b[4][2];
            #pragma unroll
            for (int p = 0; p < 2; p++) {
                const uint32_t bd = bb +
                    ((wn*32 + p*16 + (lane & 7) + ((lane >> 4) & 1)*8)*GASTR
                     + ks*16 + ((lane >> 3) & 1)*8)*2;
                LDMX4(b[2*p][0], b[2*p][1], b[2*p+1][0], b[2*p+1][1], bd);
            }
            #pragma unroll
            for (int mt = 0; mt < 2; mt++)
                #pragma unroll
                for (int nt = 0; nt < 4; nt++)
                    mma16(acc[mt][nt], a[mt][0], a[mt][1], a[mt][2], a[mt][3],
                          b[nt][0], b[nt][1]);
        }
    }

    #pragma unroll
    for (int mt = 0; mt < 2; mt++) {
        const int r0 = bm + wm*32 + mt*16 + g;
        #pragma unroll
        for (int nt = 0; nt < 4; nt++) {
            const int cc = bn + wn*32 + nt*8 + 2*tg;
            const float b0 = bias[cc], b1 = bias[cc + 1];
            float v00 = acc[mt][nt][0] + b0, v01 = acc[mt][nt][1] + b1;
            float v10 = acc[mt][nt][2] + b0, v11 = acc[mt][nt][3] + b1;
            const size_t off0 = (size_t)r0*Dd + cc;
            const size_t off1 = (size_t)(r0 + 8)*Dd + cc;
            if (RES) {
                float2 p0 = *(const float2*)(res + off0);
                float2 p1 = *(const float2*)(res + off1);
                v00 += p0.x; v01 += p0.y; v10 += p1.x; v11 += p1.y;
            }
            if (WF32) {
                float2 o0; o0.x = v00; o0.y = v01;
                float2 o1; o1.x = v10; o1.y = v11;
                *(float2*)(C32 + off0) = o0;
                *(float2*)(C32 + off1) = o1;
            }
            *(uint32_t*)(C16 + off0) = pk(v00*scale, v01*scale);
            *(uint32_t*)(C16 + off1) = pk(v10*scale, v11*scale);
        }
    }
}

__global__ __launch_bounds__(256, 2)
void gemm_in(const __half* A16, const __half* WT, const float* bias,
             float* C32, __half* C16, int K) {
    gemm16_body<false, true>(A16, WT, bias, nullptr, C32, C16, 1.f, K,
                             blockIdx.x*128, blockIdx.y*64);
}

__global__ __launch_bounds__(256, 2)
void gemm_qkv(const __half* h16, const __half* w16t,
              const float* qb, const float* kb, const float* vb,
              __half* q16, __half* k16, __half* v16, int l) {
    const int z = blockIdx.z;
    const __half* WT = w16t + WOFF_L(l, z);
    const float* bi  = (z == 0) ? qb : (z == 1) ? kb : vb;
    __half*      C16 = (z == 0) ? q16 : (z == 1) ? k16 : v16;
    const float  sc  = (z == 0) ? 0.125f : 1.f;
    gemm16_body<false, false>(h16, WT, bi, nullptr, nullptr, C16, sc, Dd,
                              blockIdx.x*128, blockIdx.y*64);
}

__global__ __launch_bounds__(256, 2)
void gemm_o(const __half* ao16, const __half* WT, const float* bias,
            const float* res, float* C32, __half* C16) {
    gemm16_body<true, true>(ao16, WT, bias, res, C32, C16, 1.f, Dd,
                            blockIdx.x*128, blockIdx.y*64);
}

// ---------------------------------------------------------------------------
// fp16 flash attention. CTA = (head, 128-row i-tile, batch), 8 warps.
// ---------------------------------------------------------------------------
#define ATSTR   72
#define AQ_HSZ  (128*ATSTR)           // 9216
#define AKV_HSZ (64*ATSTR)            // 4608
#define ASTG_H  (2*AKV_HSZ)           // 9216 / stage
#define ATTN_SMEM ((AQ_HSZ + 3*ASTG_H)*2)   // 73728 B

__global__ __launch_bounds__(256, 2)
void attn16(const __half* __restrict__ q16, const __half* __restrict__ k16,
            const __half* __restrict__ v16, const __half* __restrict__ bias_l,
            __half* __restrict__ ao16) {
    extern __shared__ __half smh[];
    const uint32_t sb = smem_u32(smh);
    const int tid  = threadIdx.x;
    const int lane = tid & 31;
    const int w    = tid >> 5;
    const int g    = lane >> 2;
    const int tg   = lane & 3;
    const int hh   = blockIdx.x;
    const int i0   = blockIdx.y * 128;
    const int bb   = blockIdx.z;
    const int w16r = w * 16;

    auto issueKV = [&](int jt) {
        const uint32_t kb = sb + (AQ_HSZ + (jt % 3) * ASTG_H) * 2;
        const uint32_t vb = kb + AKV_HSZ * 2;
        #pragma unroll
        for (int c = tid; c < 512; c += 256) {
            const int row = c >> 3, cc = c & 7;
            const size_t go = (size_t)(bb*Nn + jt*64 + row)*Dd + hh*HDd + cc*8;
            cpa16(kb + (row*ATSTR + cc*8)*2, k16 + go);
            cpa16(vb + (row*ATSTR + cc*8)*2, v16 + go);
        }
        CPA_COMMIT();
    };

    // group 0: Q + KV(0); group 1: KV(1)
    {
        #pragma unroll
        for (int c = tid; c < 1024; c += 256) {
            const int row = c >> 3, cc = c & 7;
            cpa16(sb + (row*ATSTR + cc*8)*2,
                  q16 + (size_t)(bb*Nn + i0 + row)*Dd + hh*HDd + cc*8);
        }
        const uint32_t kb = sb + AQ_HSZ*2;
        const uint32_t vb = kb + AKV_HSZ*2;
        #pragma unroll
        for (int c = tid; c < 512; c += 256) {
            const int row = c >> 3, cc = c & 7;
            const size_t go = (size_t)(bb*Nn + row)*Dd + hh*HDd + cc*8;
            cpa16(kb + (row*ATSTR + cc*8)*2, k16 + go);
            cpa16(vb + (row*ATSTR + cc*8)*2, v16 + go);
        }
        CPA_COMMIT();
        issueKV(1);
    }

    float o[8][4];
    #pragma unroll
    for (int dt = 0; dt < 8; dt++)
        #pragma unroll
        for (int e = 0; e < 4; e++) o[dt][e] = 0.f;
    float m0 = -1e30f, m1 = -1e30f, l0 = 0.f, l1 = 0.f;

    const int r0g = i0 + w16r + g;
    const __half* bp0 = bias_l + ((size_t)(bb*Hh + hh) << 20) + (size_t)r0g*Nn;
    const __half* bp1 = bp0 + 8*(size_t)Nn;

    for (int jt = 0; jt < 16; jt++) {
        // bias (fp16x2 words) — LDGs issued before the cp.async wait
        uint32_t bw0[8], bw1[8];
        #pragma unroll
        for (int nt = 0; nt < 8; nt++) {
            bw0[nt] = *(const uint32_t*)(bp0 + jt*64 + nt*8 + 2*tg);
            bw1[nt] = *(const uint32_t*)(bp1 + jt*64 + nt*8 + 2*tg);
        }

        if (jt + 1 < 16) { CPA_WAIT1(); } else { CPA_WAIT0(); }
        __syncthreads();
        if (jt + 2 < 16) issueKV(jt + 2);

        const uint32_t kbm = sb + (AQ_HSZ + (jt % 3) * ASTG_H) * 2;
        const uint32_t vbm = kbm + AKV_HSZ * 2;

        // S initialized from bias; QK MMAs accumulate on top
        float s[8][4];
        #pragma unroll
        for (int nt = 0; nt < 8; nt++) {
            const float2 f0 = __half22float2(*reinterpret_cast<__half2*>(&bw0[nt]));
            const float2 f1 = __half22float2(*reinterpret_cast<__half2*>(&bw1[nt]));
            s[nt][0] = f0.x; s[nt][1] = f0.y;
            s[nt][2] = f1.x; s[nt][3] = f1.y;
        }

        // QK: per ks, batch Q frag + all 4 K frags, THEN 8 MMAs.
        #pragma unroll
        for (int ks = 0; ks < 4; ks++) {
            uint32_t qa[4];
            const uint32_t qad = sb +
                ((w16r + (lane & 15))*ATSTR + ks*16 + (lane >> 4)*8)*2;
            LDMX4(qa[0], qa[1], qa[2], qa[3], qad);
            uint32_t kf[4][4];
            #pragma unroll
            for (int p = 0; p < 4; p++) {
                const uint32_t kad = kbm +
                    ((p*16 + (lane & 7) + ((lane >> 4) & 1)*8)*ATSTR
                     + ks*16 + ((lane >> 3) & 1)*8)*2;
                LDMX4(kf[p][0], kf[p][1], kf[p][2], kf[p][3], kad);
            }
            #pragma unroll
            for (int p = 0; p < 4; p++) {
                mma16(s[2*p],   qa[0], qa[1], qa[2], qa[3], kf[p][0], kf[p][1]);
                mma16(s[2*p+1], qa[0], qa[1], qa[2], qa[3], kf[p][2], kf[p][3]);
            }
        }

        // online softmax
        float mt0 = -1e30f, mt1 = -1e30f;
        #pragma unroll
        for (int nt = 0; nt < 8; nt++) {
            mt0 = fmaxf(mt0, fmaxf(s[nt][0], s[nt][1]));
            mt1 = fmaxf(mt1, fmaxf(s[nt][2], s[nt][3]));
        }
        mt0 = fmaxf(mt0, __shfl_xor_sync(0xffffffffu, mt0, 1));
        mt0 = fmaxf(mt0, __shfl_xor_sync(0xffffffffu, mt0, 2));
        mt1 = fmaxf(mt1, __shfl_xor_sync(0xffffffffu, mt1, 1));
        mt1 = fmaxf(mt1, __shfl_xor_sync(0xffffffffu, mt1, 2));
        const float mn0 = fmaxf(m0, mt0), mn1 = fmaxf(m1, mt1);
        const float al0 = __expf(m0 - mn0), al1 = __expf(m1 - mn1);
        m0 = mn0; m1 = mn1;
        float rs0 = 0.f, rs1 = 0.f;
        #pragma unroll
        for (int nt = 0; nt < 8; nt++) {
            s[nt][0] = __expf(s[nt][0] - mn0); rs0 += s[nt][0];
            s[nt][1] = __expf(s[nt][1] - mn0); rs0 += s[nt][1];
            s[nt][2] = __expf(s[nt][2] - mn1); rs1 += s[nt][2];
            s[nt][3] = __expf(s[nt][3] - mn1); rs1 += s[nt][3];
        }
        rs0 += __shfl_xor_sync(0xffffffffu, rs0, 1);
        rs0 += __shfl_xor_sync(0xffffffffu, rs0, 2);
        rs1 += __shfl_xor_sync(0xffffffffu, rs1, 1);
        rs1 += __shfl_xor_sync(0xffffffffu, rs1, 2);
        l0 = l0*al0 + rs0; l1 = l1*al1 + rs1;
        #pragma unroll
        for (int dt = 0; dt < 8; dt++) {
            o[dt][0] *= al0; o[dt][1] *= al0;
            o[dt][2] *= al1; o[dt][3] *= al1;
        }

        // PV: per c, pack P frags + batch all 4 V frags, THEN 8 MMAs.
        #pragma unroll
        for (int c = 0; c < 4; c++) {
            const uint32_t pa0 = pk(s[2*c][0],   s[2*c][1]);
            const uint32_t pa1 = pk(s[2*c][2],   s[2*c][3]);
            const uint32_t pa2 = pk(s[2*c+1][0], s[2*c+1][1]);
            const uint32_t pa3 = pk(s[2*c+1][2], s[2*c+1][3]);
            uint32_t vf[4][4];
            #pragma unroll
            for (int pd = 0; pd < 4; pd++) {
                const uint32_t vad = vbm +
                    ((c*16 + (lane & 7) + ((lane >> 3) & 1)*8)*ATSTR
                     + pd*16 + ((lane >> 4) & 1)*8)*2;
                LDMX4T(vf[pd][0], vf[pd][1], vf[pd][2], vf[pd][3], vad);
            }
            #pragma unroll
            for (int pd = 0; pd < 4; pd++) {
                mma16(o[2*pd],   pa0, pa1, pa2, pa3, vf[pd][0], vf[pd][1]);
                mma16(o[2*pd+1], pa0, pa1, pa2, pa3, vf[pd][2], vf[pd][3]);
            }
        }
    }

    const float inv0 = 1.f / l0, inv1 = 1.f / l1;
    __half* op0 = ao16 + (size_t)(bb*Nn + r0g    )*Dd + hh*HDd;
    __half* op1 = ao16 + (size_t)(bb*Nn + r0g + 8)*Dd + hh*HDd;
    #pragma unroll
    for (int dt = 0; dt < 8; dt++) {
        const int dc = dt*8 + 2*tg;
        *(uint32_t*)(op0 + dc) = pk(o[dt][0]*inv0, o[dt][1]*inv0);
        *(uint32_t*)(op1 + dc) = pk(o[dt][2]*inv1, o[dt][3]*inv1);
    }
}

// ---------------------------------------------------------------------------
// LayerNorm: one block (128 threads) per row of 512.
// ---------------------------------------------------------------------------
__global__ __launch_bounds__(128)
void ln_kernel(const float* __restrict__ h, const float* __restrict__ g,
               const float* __restrict__ b, float* __restrict__ out) {
    const int row = blockIdx.x;
    const int tid = threadIdx.x;
    const float4 x = *(const float4*)(h + (size_t)row*Dd + tid*4);
    float s  = x.x + x.y + x.z + x.w;
    float s2 = x.x*x.x + x.y*x.y + x.z*x.z + x.w*x.w;
    #pragma unroll
    for (int off = 16; off >= 1; off >>= 1) {
        s  += __shfl_xor_sync(0xffffffffu, s,  off);
        s2 += __shfl_xor_sync(0xffffffffu, s2, off);
    }
    __shared__ float ws[4], ws2[4];
    if ((tid & 31) == 0) { ws[tid>>5] = s; ws2[tid>>5] = s2; }
    __syncthreads();
    s  = ws[0] + ws[1] + ws[2] + ws[3];
    s2 = ws2[0] + ws2[1] + ws2[2] + ws2[3];
    const float mu  = s * (1.f/Dd);
    const float var = s2 * (1.f/Dd) - mu*mu;
    const float rstd = rsqrtf(var + 1e-5f);
    const float4 g4 = *(const float4*)(g + tid*4);
    const float4 b4 = *(const float4*)(b + tid*4);
    float4 r;
    r.x = (x.x - mu)*rstd*g4.x + b4.x;
    r.y = (x.y - mu)*rstd*g4.y + b4.y;
    r.z = (x.z - mu)*rstd*g4.z + b4.z;
    r.w = (x.w - mu)*rstd*g4.w + b4.w;
    *(float4*)(out + (size_t)row*Dd + tid*4) = r;
}

// ---------------------------------------------------------------------------
extern "C" void kernel_launch(void* const* d_in, const int* in_sizes, int n_in,
                              void* d_out, int out_size) {
    (void)in_sizes; (void)n_in; (void)out_size;
    const float* x    = (const float*)d_in[0];
    const float* edges= (const float*)d_in[1];
    const float* in_w = (const float*)d_in[2];
    const float* in_b = (const float*)d_in[3];
    const float* qw   = (const float*)d_in[4];
    const float* qb   = (const float*)d_in[5];
    const float* kw   = (const float*)d_in[6];
    const float* kb   = (const float*)d_in[7];
    const float* vw   = (const float*)d_in[8];
    const float* vb   = (const float*)d_in[9];
    const float* ow   = (const float*)d_in[10];
    const float* ob   = (const float*)d_in[11];
    const float* ew   = (const float*)d_in[12];
    const float* eb   = (const float*)d_in[13];
    const float* ln_g = (const float*)d_in[14];
    const float* ln_b = (const float*)d_in[15];
    float* out = (float*)d_out;

    float *h;
    __half *h16, *x16, *q16, *k16, *v16, *ao16, *w16t, *bias16;
    cudaGetSymbolAddress((void**)&h,     g_h);
    cudaGetSymbolAddress((void**)&h16,   g_h16);
    cudaGetSymbolAddress((void**)&x16,   g_x16);
    cudaGetSymbolAddress((void**)&q16,   g_q16);
    cudaGetSymbolAddress((void**)&k16,   g_k16);
    cudaGetSymbolAddress((void**)&v16,   g_v16);
    cudaGetSymbolAddress((void**)&ao16,  g_ao16);
    cudaGetSymbolAddress((void**)&w16t,  g_w16t);
    cudaGetSymbolAddress((void**)&bias16,g_bias16);

    cudaFuncSetAttribute(gemm_in,  cudaFuncAttributeMaxDynamicSharedMemorySize, GEMM_SMEM);
    cudaFuncSetAttribute(gemm_qkv, cudaFuncAttributeMaxDynamicSharedMemorySize, GEMM_SMEM);
    cudaFuncSetAttribute(gemm_o,   cudaFuncAttributeMaxDynamicSharedMemorySize, GEMM_SMEM);
    cudaFuncSetAttribute(attn16,   cudaFuncAttributeMaxDynamicSharedMemorySize, ATTN_SMEM);

    // Fork-join: edge-bias precompute runs on a side stream, overlapped with
    // the weight/x conversion and the GEMM chain. attn16(l) joins on evL[l].
    cudaStream_t s2;
    cudaStreamCreateWithFlags(&s2, cudaStreamNonBlocking);
    cudaEvent_t evF, evL[Ll];
    cudaEventCreateWithFlags(&evF, cudaEventDisableTiming);
    for (int l = 0; l < Ll; l++)
        cudaEventCreateWithFlags(&evL[l], cudaEventDisableTiming);

    cudaEventRecord(evF, 0);
    cudaStreamWaitEvent(s2, evF, 0);
    for (int l = 0; l < Ll; l++) {
        edgeproj1<<<Bsz*Nn*(Nn/8)/256, 256, 0, s2>>>(edges, ew, eb, bias16, l);
        cudaEventRecord(evL[l], s2);
    }

    // main stream
    wtrans<<<dim3(16,16,13), dim3(32,8)>>>(in_w, qw, kw, vw, ow, w16t);
    cvt_x16<<<BNROWS*IND/(256*8), 256>>>(x, x16);

    dim3 gg(BNROWS/128, Dd/64);            // (32, 8)
    dim3 gq(BNROWS/128, Dd/64, 3);
    dim3 ag(Hh, Nn/128, Bsz);              // (8, 8, 4)

    gemm_in<<<gg, 256, GEMM_SMEM>>>(x16, w16t, in_b, h, h16, IND);

    for (int l = 0; l < Ll; l++) {
        gemm_qkv<<<gq, 256, GEMM_SMEM>>>(h16, w16t, qb + l*Dd, kb + l*Dd, vb + l*Dd,
                                         q16, k16, v16, l);
        cudaStreamWaitEvent(0, evL[l], 0);
        attn16<<<ag, 256, ATTN_SMEM>>>(q16, k16, v16,
                                       bias16 + (size_t)l*Bsz*Hh*Nn*Nn, ao16);
        gemm_o<<<gg, 256, GEMM_SMEM>>>(ao16, w16t + WOFF_L(l,3), ob + l*Dd,
                                       h, h, h16);
    }

    ln_kernel<<<BNROWS, 128>>>(h, ln_g, ln_b, out);
}

// round 16
// speedup vs baseline: 1.0970x; 1.0970x over previous
#include <cuda_runtime.h>
#include <cuda_fp16.h>
#include <math.h>
#include <stdint.h>

#define Bsz 4
#define Nn 1024
#define IND 128
#define Dd 512
#define Hh 8
#define HDd 64
#define Ee 4
#define Ll 3
#define BNROWS (Bsz*Nn)   // 4096
#define LOG2E 1.44269504088896f

// ---------------------------------------------------------------------------
// Scratch (device globals: no cudaMalloc allowed)
// ---------------------------------------------------------------------------
__device__ float  g_h   [BNROWS*Dd];
__device__ __half g_h16 [BNROWS*Dd];
__device__ __half g_x16 [BNROWS*IND];
__device__ __half g_q16 [BNROWS*Dd];
__device__ __half g_k16 [BNROWS*Dd];
__device__ __half g_v16 [BNROWS*Dd];
__device__ __half g_ao16[BNROWS*Dd];
// transposed fp16 weights: in_w^T [512][128], then per (l, {q,k,v,o}): [512][512]
__device__ __half g_w16t[512*128 + 12*512*512];
// fp16 copy of edges [B][N][N][E] (L2-resident: 33.5 MB)
__device__ __half g_e16[(size_t)Bsz*Nn*Nn*Ee];

#define WOFF_L(l, m) (512*128 + ((size_t)((l)*4 + (m)))*512*512)

// ---------------------------------------------------------------------------
// helpers
// ---------------------------------------------------------------------------
__device__ __forceinline__ uint32_t pk(float x, float y) {
    __half2 h = __floats2half2_rn(x, y);
    return *reinterpret_cast<uint32_t*>(&h);
}

__device__ __forceinline__ uint32_t smem_u32(const void* p) {
    uint32_t a;
    asm("{ .reg .u64 t; cvta.to.shared.u64 t, %1; cvt.u32.u64 %0, t; }"
        : "=r"(a) : "l"(p));
    return a;
}

__device__ __forceinline__ void mma16(float* c, uint32_t a0, uint32_t a1,
                                      uint32_t a2, uint32_t a3,
                                      uint32_t b0, uint32_t b1) {
    asm volatile(
        "mma.sync.aligned.m16n8k16.row.col.f32.f16.f16.f32 "
        "{%0,%1,%2,%3},{%4,%5,%6,%7},{%8,%9},{%0,%1,%2,%3};"
        : "+f"(c[0]), "+f"(c[1]), "+f"(c[2]), "+f"(c[3])
        : "r"(a0), "r"(a1), "r"(a2), "r"(a3), "r"(b0), "r"(b1));
}

#define LDMX4(r0,r1,r2,r3,addr) \
    asm volatile("ldmatrix.sync.aligned.m8n8.x4.shared.b16 {%0,%1,%2,%3}, [%4];" \
                 : "=r"(r0),"=r"(r1),"=r"(r2),"=r"(r3) : "r"(addr))
#define LDMX4T(r0,r1,r2,r3,addr) \
    asm volatile("ldmatrix.sync.aligned.m8n8.x4.trans.shared.b16 {%0,%1,%2,%3}, [%4];" \
                 : "=r"(r0),"=r"(r1),"=r"(r2),"=r"(r3) : "r"(addr))

__device__ __forceinline__ void cpa16(uint32_t dst, const void* src) {
    asm volatile("cp.async.cg.shared.global [%0], [%1], 16;" :: "r"(dst), "l"(src));
}
#define CPA_COMMIT() asm volatile("cp.async.commit_group;")
#define CPA_WAIT1()  asm volatile("cp.async.wait_group 1;")
#define CPA_WAIT0()  asm volatile("cp.async.wait_group 0;")

// ---------------------------------------------------------------------------
// Pre-pass 1: weight convert + transpose -> fp16 [n][k]
// ---------------------------------------------------------------------------
__global__ void wtrans(const float* __restrict__ in_w, const float* __restrict__ qw,
                       const float* __restrict__ kw, const float* __restrict__ vw,
                       const float* __restrict__ ow, __half* __restrict__ w16t) {
    const int z = blockIdx.z;
    const float* src; int K; size_t doff;
    if (z == 0) { src = in_w; K = IND; doff = 0; }
    else {
        const int li = (z - 1) >> 2, m = (z - 1) & 3;
        const float* base = (m == 0) ? qw : (m == 1) ? kw : (m == 2) ? vw : ow;
        src = base + (size_t)li * Dd * Dd;
        K = Dd; doff = 512*128 + (size_t)(z - 1) * 512 * 512;
    }
    const int k0 = blockIdx.x * 32, n0 = blockIdx.y * 32;
    if (k0 >= K) return;
    __shared__ float tile[32][33];
    const int tx = threadIdx.x, ty = threadIdx.y;
    #pragma unroll
    for (int i = 0; i < 4; i++)
        tile[ty + i*8][tx] = src[(size_t)(k0 + ty + i*8) * Dd + n0 + tx];
    __syncthreads();
    #pragma unroll
    for (int i = 0; i < 4; i++)
        w16t[doff + (size_t)(n0 + ty + i*8) * K + k0 + tx] =
            __float2half(tile[tx][ty + i*8]);
}

// Pre-pass 2: x -> fp16
__global__ void cvt_x16(const float* __restrict__ x, __half* __restrict__ x16) {
    const int i = (blockIdx.x * 256 + threadIdx.x) * 8;
    float4 a = *(const float4*)(x + i);
    float4 b = *(const float4*)(x + i + 4);
    uint4 u;
    u.x = pk(a.x, a.y); u.y = pk(a.z, a.w);
    u.z = pk(b.x, b.y); u.w = pk(b.z, b.w);
    *(uint4*)(x16 + i) = u;
}

// Pre-pass 3: edges -> fp16 (elementwise; replaces the 268 MB edgeproj)
__global__ void cvt_e16(const float* __restrict__ e, __half* __restrict__ e16) {
    const size_t i = ((size_t)blockIdx.x * 256 + threadIdx.x) * 8;
    float4 a = *(const float4*)(e + i);
    float4 b = *(const float4*)(e + i + 4);
    uint4 u;
    u.x = pk(a.x, a.y); u.y = pk(a.z, a.w);
    u.z = pk(b.x, b.y); u.w = pk(b.z, b.w);
    *(uint4*)(e16 + i) = u;
}

// ---------------------------------------------------------------------------
// fp16 GEMM: C[M x 512] = A16[M x K] @ W16T^T + bias (+ res)
// CTA 128x64, BK=32, 3-stage cp.async, ldmatrix fragments.
// Final tile drains with wait_group 0 (R10 race fix).
// ---------------------------------------------------------------------------
#define GASTR 40
#define GA_HSZ (128*GASTR)        // 5120 halfs
#define GB_HSZ (64*GASTR)         // 2560 halfs
#define GSTG_H (GA_HSZ + GB_HSZ)  // 7680 halfs / stage
#define GEMM_SMEM (3*GSTG_H*2)    // 46080 B

template<bool RES, bool WF32>
__device__ __forceinline__
void gemm16_body(const __half* __restrict__ A16, const __half* __restrict__ WT,
                 const float* __restrict__ bias, const float* __restrict__ res,
                 float* __restrict__ C32, __half* __restrict__ C16,
                 float scale, int K, int bm, int bn) {
    extern __shared__ __half smh[];
    const uint32_t sb = smem_u32(smh);
    const int tid  = threadIdx.x;
    const int lane = tid & 31;
    const int warp = tid >> 5;
    const int wm   = warp & 3;
    const int wn   = warp >> 2;
    const int g    = lane >> 2;
    const int tg   = lane & 3;

    auto issue = [&](int t) {
        const int k0 = t << 5;
        const uint32_t ab = sb + ((t % 3) * GSTG_H) * 2;
        const uint32_t bb = ab + GA_HSZ * 2;
        #pragma unroll
        for (int c = tid; c < 512; c += 256) {
            const int row = c >> 2, cc = c & 3;
            cpa16(ab + (row*GASTR + cc*8)*2,
                  A16 + (size_t)(bm + row)*K + k0 + cc*8);
        }
        { const int row = tid >> 2, cc = tid & 3;
          cpa16(bb + (row*GASTR + cc*8)*2,
                WT + (size_t)(bn + row)*K + k0 + cc*8); }
        CPA_COMMIT();
    };

    float acc[2][4][4];
    #pragma unroll
    for (int mt = 0; mt < 2; mt++)
        #pragma unroll
        for (int nt = 0; nt < 4; nt++)
            #pragma unroll
            for (int e = 0; e < 4; e++) acc[mt][nt][e] = 0.f;

    const int T = K >> 5;
    issue(0); issue(1);

    for (int t = 0; t < T; t++) {
        if (t + 1 < T) { CPA_WAIT1(); } else { CPA_WAIT0(); }
        __syncthreads();
        if (t + 2 < T) issue(t + 2);

        const uint32_t ab = sb + ((t % 3) * GSTG_H) * 2;
        const uint32_t bb = ab + GA_HSZ * 2;
        #pragma unroll
        for (int ks = 0; ks < 2; ks++) {
            uint32_t a[2][4];
            #pragma unroll
            for (int mt = 0; mt < 2; mt++) {
                const uint32_t ad = ab +
                    ((wm*32 + mt*16 + (lane & 15))*GASTR + ks*16 + (lane >> 4)*8)*2;
                LDMX4(a[mt][0], a[mt][1], a[mt][2], a[mt][3], ad);
            }
            uint32_t b[4][2];
            #pragma unroll
            for (int p = 0; p < 2; p++) {
                const uint32_t bd = bb +
                    ((wn*32 + p*16 + (lane & 7) + ((lane >> 4) & 1)*8)*GASTR
                     + ks*16 + ((lane >> 3) & 1)*8)*2;
                LDMX4(b[2*p][0], b[2*p][1], b[2*p+1][0], b[2*p+1][1], bd);
            }
            #pragma unroll
            for (int mt = 0; mt < 2; mt++)
                #pragma unroll
                for (int nt = 0; nt < 4; nt++)
                    mma16(acc[mt][nt], a[mt][0], a[mt][1], a[mt][2], a[mt][3],
                          b[nt][0], b[nt][1]);
        }
    }

    #pragma unroll
    for (int mt = 0; mt < 2; mt++) {
        const int r0 = bm + wm*32 + mt*16 + g;
        #pragma unroll
        for (int nt = 0; nt < 4; nt++) {
            const int cc = bn + wn*32 + nt*8 + 2*tg;
            const float b0 = bias[cc], b1 = bias[cc + 1];
            float v00 = acc[mt][nt][0] + b0, v01 = acc[mt][nt][1] + b1;
            float v10 = acc[mt][nt][2] + b0, v11 = acc[mt][nt][3] + b1;
            const size_t off0 = (size_t)r0*Dd + cc;
            const size_t off1 = (size_t)(r0 + 8)*Dd + cc;
            if (RES) {
                float2 p0 = *(const float2*)(res + off0);
                float2 p1 = *(const float2*)(res + off1);
                v00 += p0.x; v01 += p0.y; v10 += p1.x; v11 += p1.y;
            }
            if (WF32) {
                float2 o0; o0.x = v00; o0.y = v01;
                float2 o1; o1.x = v10; o1.y = v11;
                *(float2*)(C32 + off0) = o0;
                *(float2*)(C32 + off1) = o1;
            }
            *(uint32_t*)(C16 + off0) = pk(v00*scale, v01*scale);
            *(uint32_t*)(C16 + off1) = pk(v10*scale, v11*scale);
        }
    }
}

__global__ __launch_bounds__(256, 2)
void gemm_in(const __half* A16, const __half* WT, const float* bias,
             float* C32, __half* C16, int K) {
    gemm16_body<false, true>(A16, WT, bias, nullptr, C32, C16, 1.f, K,
                             blockIdx.x*128, blockIdx.y*64);
}

__global__ __launch_bounds__(256, 2)
void gemm_qkv(const __half* h16, const __half* w16t,
              const float* qb, const float* kb, const float* vb,
              __half* q16, __half* k16, __half* v16, int l) {
    const int z = blockIdx.z;
    const __half* WT = w16t + WOFF_L(l, z);
    const float* bi  = (z == 0) ? qb : (z == 1) ? kb : vb;
    __half*      C16 = (z == 0) ? q16 : (z == 1) ? k16 : v16;
    // Q pre-scaled by 0.125*log2(e) so softmax can run in exp2 domain.
    const float  sc  = (z == 0) ? 0.125f * LOG2E : 1.f;
    gemm16_body<false, false>(h16, WT, bi, nullptr, nullptr, C16, sc, Dd,
                              blockIdx.x*128, blockIdx.y*64);
}

__global__ __launch_bounds__(256, 2)
void gemm_o(const __half* ao16, const __half* WT, const float* bias,
            const float* res, float* C32, __half* C16) {
    gemm16_body<true, true>(ao16, WT, bias, res, C32, C16, 1.f, Dd,
                            blockIdx.x*128, blockIdx.y*64);
}

// ---------------------------------------------------------------------------
// fp16 flash attention. CTA = (head, 128-row i-tile, batch), 8 warps.
// Edge bias computed inline from fp16 edges (L2-resident); softmax in exp2
// domain (Q and ew/eb pre-scaled by log2 e).
// ---------------------------------------------------------------------------
#define ATSTR   72
#define AQ_HSZ  (128*ATSTR)           // 9216
#define AKV_HSZ (64*ATSTR)            // 4608
#define ASTG_H  (2*AKV_HSZ)           // 9216 / stage
#define ATTN_SMEM ((AQ_HSZ + 3*ASTG_H)*2)   // 73728 B

__global__ __launch_bounds__(256, 2)
void attn16(const __half* __restrict__ q16, const __half* __restrict__ k16,
            const __half* __restrict__ v16, const __half* __restrict__ e16,
            const float* __restrict__ ew, const float* __restrict__ ebv,
            __half* __restrict__ ao16) {
    extern __shared__ __half smh[];
    const uint32_t sb = smem_u32(smh);
    const int tid  = threadIdx.x;
    const int lane = tid & 31;
    const int w    = tid >> 5;
    const int g    = lane >> 2;
    const int tg   = lane & 3;
    const int hh   = blockIdx.x;
    const int i0   = blockIdx.y * 128;
    const int bb   = blockIdx.z;
    const int w16r = w * 16;

    // per-head edge weights, pre-scaled into the exp2 domain
    const float ew0 = ew[hh]        * LOG2E;
    const float ew1 = ew[Hh + hh]   * LOG2E;
    const float ew2 = ew[2*Hh + hh] * LOG2E;
    const float ew3 = ew[3*Hh + hh] * LOG2E;
    const float ebh = ebv[hh]       * LOG2E;

    auto issueKV = [&](int jt) {
        const uint32_t kb = sb + (AQ_HSZ + (jt % 3) * ASTG_H) * 2;
        const uint32_t vb = kb + AKV_HSZ * 2;
        #pragma unroll
        for (int c = tid; c < 512; c += 256) {
            const int row = c >> 3, cc = c & 7;
            const size_t go = (size_t)(bb*Nn + jt*64 + row)*Dd + hh*HDd + cc*8;
            cpa16(kb + (row*ATSTR + cc*8)*2, k16 + go);
            cpa16(vb + (row*ATSTR + cc*8)*2, v16 + go);
        }
        CPA_COMMIT();
    };

    // group 0: Q + KV(0); group 1: KV(1)
    {
        #pragma unroll
        for (int c = tid; c < 1024; c += 256) {
            const int row = c >> 3, cc = c & 7;
            cpa16(sb + (row*ATSTR + cc*8)*2,
                  q16 + (size_t)(bb*Nn + i0 + row)*Dd + hh*HDd + cc*8);
        }
        const uint32_t kb = sb + AQ_HSZ*2;
        const uint32_t vb = kb + AKV_HSZ*2;
        #pragma unroll
        for (int c = tid; c < 512; c += 256) {
            const int row = c >> 3, cc = c & 7;
            const size_t go = (size_t)(bb*Nn + row)*Dd + hh*HDd + cc*8;
            cpa16(kb + (row*ATSTR + cc*8)*2, k16 + go);
            cpa16(vb + (row*ATSTR + cc*8)*2, v16 + go);
        }
        CPA_COMMIT();
        issueKV(1);
    }

    float o[8][4];
    #pragma unroll
    for (int dt = 0; dt < 8; dt++)
        #pragma unroll
        for (int e = 0; e < 4; e++) o[dt][e] = 0.f;
    float m0 = -1e30f, m1 = -1e30f, l0 = 0.f, l1 = 0.f;

    const int r0g = i0 + w16r + g;
    // fp16 edge rows for this thread's two i-rows (Ee=4 halfs per j)
    const __half* ep0 = e16 + ((size_t)(bb*Nn + r0g))*Nn*Ee;
    const __half* ep1 = ep0 + (size_t)8*Nn*Ee;

    for (int jt = 0; jt < 16; jt++) {
        if (jt + 1 < 16) { CPA_WAIT1(); } else { CPA_WAIT0(); }
        __syncthreads();
        if (jt + 2 < 16) issueKV(jt + 2);

        const uint32_t kbm = sb + (AQ_HSZ + (jt % 3) * ASTG_H) * 2;
        const uint32_t vbm = kbm + AKV_HSZ * 2;

        // S initialized from inline edge bias (exp2 domain)
        float s[8][4];
        #pragma unroll
        for (int nt = 0; nt < 8; nt++) {
            const size_t joff = (size_t)(jt*64 + nt*8 + 2*tg) * Ee;
            // 2 adjacent j's x 4 e-values = one 16B load per row
            const uint4 ua = *(const uint4*)(ep0 + joff);
            const uint4 ub = *(const uint4*)(ep1 + joff);
            const float2 a01 = __half22float2(*reinterpret_cast<const __half2*>(&ua.x));
            const float2 a23 = __half22float2(*reinterpret_cast<const __half2*>(&ua.y));
            const float2 c01 = __half22float2(*reinterpret_cast<const __half2*>(&ua.z));
            const float2 c23 = __half22float2(*reinterpret_cast<const __half2*>(&ua.w));
            const float2 d01 = __half22float2(*reinterpret_cast<const __half2*>(&ub.x));
            const float2 d23 = __half22float2(*reinterpret_cast<const __half2*>(&ub.y));
            const float2 f01 = __half22float2(*reinterpret_cast<const __half2*>(&ub.z));
            const float2 f23 = __half22float2(*reinterpret_cast<const __half2*>(&ub.w));
            s[nt][0] = fmaf(a01.x,ew0, fmaf(a01.y,ew1, fmaf(a23.x,ew2, fmaf(a23.y,ew3, ebh))));
            s[nt][1] = fmaf(c01.x,ew0, fmaf(c01.y,ew1, fmaf(c23.x,ew2, fmaf(c23.y,ew3, ebh))));
            s[nt][2] = fmaf(d01.x,ew0, fmaf(d01.y,ew1, fmaf(d23.x,ew2, fmaf(d23.y,ew3, ebh))));
            s[nt][3] = fmaf(f01.x,ew0, fmaf(f01.y,ew1, fmaf(f23.x,ew2, fmaf(f23.y,ew3, ebh))));
        }

        // QK: per ks, batch Q frag + all 4 K frags, THEN 8 MMAs.
        #pragma unroll
        for (int ks = 0; ks < 4; ks++) {
            uint32_t qa[4];
            const uint32_t qad = sb +
                ((w16r + (lane & 15))*ATSTR + ks*16 + (lane >> 4)*8)*2;
            LDMX4(qa[0], qa[1], qa[2], qa[3], qad);
            uint32_t kf[4][4];
            #pragma unroll
            for (int p = 0; p < 4; p++) {
                const uint32_t kad = kbm +
                    ((p*16 + (lane & 7) + ((lane >> 4) & 1)*8)*ATSTR
                     + ks*16 + ((lane >> 3) & 1)*8)*2;
                LDMX4(kf[p][0], kf[p][1], kf[p][2], kf[p][3], kad);
            }
            #pragma unroll
            for (int p = 0; p < 4; p++) {
                mma16(s[2*p],   qa[0], qa[1], qa[2], qa[3], kf[p][0], kf[p][1]);
                mma16(s[2*p+1], qa[0], qa[1], qa[2], qa[3], kf[p][2], kf[p][3]);
            }
        }

        // online softmax (exp2 domain)
        float mt0 = -1e30f, mt1 = -1e30f;
        #pragma unroll
        for (int nt = 0; nt < 8; nt++) {
            mt0 = fmaxf(mt0, fmaxf(s[nt][0], s[nt][1]));
            mt1 = fmaxf(mt1, fmaxf(s[nt][2], s[nt][3]));
        }
        mt0 = fmaxf(mt0, __shfl_xor_sync(0xffffffffu, mt0, 1));
        mt0 = fmaxf(mt0, __shfl_xor_sync(0xffffffffu, mt0, 2));
        mt1 = fmaxf(mt1, __shfl_xor_sync(0xffffffffu, mt1, 1));
        mt1 = fmaxf(mt1, __shfl_xor_sync(0xffffffffu, mt1, 2));
        const float mn0 = fmaxf(m0, mt0), mn1 = fmaxf(m1, mt1);
        const float al0 = exp2f(m0 - mn0), al1 = exp2f(m1 - mn1);
        m0 = mn0; m1 = mn1;
        float rs0 = 0.f, rs1 = 0.f;
        #pragma unroll
        for (int nt = 0; nt < 8; nt++) {
            s[nt][0] = exp2f(s[nt][0] - mn0); rs0 += s[nt][0];
            s[nt][1] = exp2f(s[nt][1] - mn0); rs0 += s[nt][1];
            s[nt][2] = exp2f(s[nt][2] - mn1); rs1 += s[nt][2];
            s[nt][3] = exp2f(s[nt][3] - mn1); rs1 += s[nt][3];
        }
        rs0 += __shfl_xor_sync(0xffffffffu, rs0, 1);
        rs0 += __shfl_xor_sync(0xffffffffu, rs0, 2);
        rs1 += __shfl_xor_sync(0xffffffffu, rs1, 1);
        rs1 += __shfl_xor_sync(0xffffffffu, rs1, 2);
        l0 = l0*al0 + rs0; l1 = l1*al1 + rs1;
        #pragma unroll
        for (int dt = 0; dt < 8; dt++) {
            o[dt][0] *= al0; o[dt][1] *= al0;
            o[dt][2] *= al1; o[dt][3] *= al1;
        }

        // PV: per c, pack P frags + batch all 4 V frags, THEN 8 MMAs.
        #pragma unroll
        for (int c = 0; c < 4; c++) {
            const uint32_t pa0 = pk(s[2*c][0],   s[2*c][1]);
            const uint32_t pa1 = pk(s[2*c][2],   s[2*c][3]);
            const uint32_t pa2 = pk(s[2*c+1][0], s[2*c+1][1]);
            const uint32_t pa3 = pk(s[2*c+1][2], s[2*c+1][3]);
            uint32_t vf[4][4];
            #pragma unroll
            for (int pd = 0; pd < 4; pd++) {
                const uint32_t vad = vbm +
                    ((c*16 + (lane & 7) + ((lane >> 3) & 1)*8)*ATSTR
                     + pd*16 + ((lane >> 4) & 1)*8)*2;
                LDMX4T(vf[pd][0], vf[pd][1], vf[pd][2], vf[pd][3], vad);
            }
            #pragma unroll
            for (int pd = 0; pd < 4; pd++) {
                mma16(o[2*pd],   pa0, pa1, pa2, pa3, vf[pd][0], vf[pd][1]);
                mma16(o[2*pd+1], pa0, pa1, pa2, pa3, vf[pd][2], vf[pd][3]);
            }
        }
    }

    const float inv0 = 1.f / l0, inv1 = 1.f / l1;
    __half* op0 = ao16 + (size_t)(bb*Nn + r0g    )*Dd + hh*HDd;
    __half* op1 = ao16 + (size_t)(bb*Nn + r0g + 8)*Dd + hh*HDd;
    #pragma unroll
    for (int dt = 0; dt < 8; dt++) {
        const int dc = dt*8 + 2*tg;
        *(uint32_t*)(op0 + dc) = pk(o[dt][0]*inv0, o[dt][1]*inv0);
        *(uint32_t*)(op1 + dc) = pk(o[dt][2]*inv1, o[dt][3]*inv1);
    }
}

// ---------------------------------------------------------------------------
// LayerNorm: one block (128 threads) per row of 512.
// ---------------------------------------------------------------------------
__global__ __launch_bounds__(128)
void ln_kernel(const float* __restrict__ h, const float* __restrict__ g,
               const float* __restrict__ b, float* __restrict__ out) {
    const int row = blockIdx.x;
    const int tid = threadIdx.x;
    const float4 x = *(const float4*)(h + (size_t)row*Dd + tid*4);
    float s  = x.x + x.y + x.z + x.w;
    float s2 = x.x*x.x + x.y*x.y + x.z*x.z + x.w*x.w;
    #pragma unroll
    for (int off = 16; off >= 1; off >>= 1) {
        s  += __shfl_xor_sync(0xffffffffu, s,  off);
        s2 += __shfl_xor_sync(0xffffffffu, s2, off);
    }
    __shared__ float ws[4], ws2[4];
    if ((tid & 31) == 0) { ws[tid>>5] = s; ws2[tid>>5] = s2; }
    __syncthreads();
    s  = ws[0] + ws[1] + ws[2] + ws[3];
    s2 = ws2[0] + ws2[1] + ws2[2] + ws2[3];
    const float mu  = s * (1.f/Dd);
    const float var = s2 * (1.f/Dd) - mu*mu;
    const float rstd = rsqrtf(var + 1e-5f);
    const float4 g4 = *(const float4*)(g + tid*4);
    const float4 b4 = *(const float4*)(b + tid*4);
    float4 r;
    r.x = (x.x - mu)*rstd*g4.x + b4.x;
    r.y = (x.y - mu)*rstd*g4.y + b4.y;
    r.z = (x.z - mu)*rstd*g4.z + b4.z;
    r.w = (x.w - mu)*rstd*g4.w + b4.w;
    *(float4*)(out + (size_t)row*Dd + tid*4) = r;
}

// ---------------------------------------------------------------------------
extern "C" void kernel_launch(void* const* d_in, const int* in_sizes, int n_in,
                              void* d_out, int out_size) {
    (void)in_sizes; (void)n_in; (void)out_size;
    const float* x    = (const float*)d_in[0];
    const float* edges= (const float*)d_in[1];
    const float* in_w = (const float*)d_in[2];
    const float* in_b = (const float*)d_in[3];
    const float* qw   = (const float*)d_in[4];
    const float* qb   = (const float*)d_in[5];
    const float* kw   = (const float*)d_in[6];
    const float* kb   = (const float*)d_in[7];
    const float* vw   = (const float*)d_in[8];
    const float* vb   = (const float*)d_in[9];
    const float* ow   = (const float*)d_in[10];
    const float* ob   = (const float*)d_in[11];
    const float* ew   = (const float*)d_in[12];
    const float* eb   = (const float*)d_in[13];
    const float* ln_g = (const float*)d_in[14];
    const float* ln_b = (const float*)d_in[15];
    float* out = (float*)d_out;

    float *h;
    __half *h16, *x16, *q16, *k16, *v16, *ao16, *w16t, *e16;
    cudaGetSymbolAddress((void**)&h,    g_h);
    cudaGetSymbolAddress((void**)&h16,  g_h16);
    cudaGetSymbolAddress((void**)&x16,  g_x16);
    cudaGetSymbolAddress((void**)&q16,  g_q16);
    cudaGetSymbolAddress((void**)&k16,  g_k16);
    cudaGetSymbolAddress((void**)&v16,  g_v16);
    cudaGetSymbolAddress((void**)&ao16, g_ao16);
    cudaGetSymbolAddress((void**)&w16t, g_w16t);
    cudaGetSymbolAddress((void**)&e16,  g_e16);

    cudaFuncSetAttribute(gemm_in,  cudaFuncAttributeMaxDynamicSharedMemorySize, GEMM_SMEM);
    cudaFuncSetAttribute(gemm_qkv, cudaFuncAttributeMaxDynamicSharedMemorySize, GEMM_SMEM);
    cudaFuncSetAttribute(gemm_o,   cudaFuncAttributeMaxDynamicSharedMemorySize, GEMM_SMEM);
    cudaFuncSetAttribute(attn16,   cudaFuncAttributeMaxDynamicSharedMemorySize, ATTN_SMEM);

    // pre-passes (single stream; R14's fork-join regressed — no concurrency)
    wtrans<<<dim3(16,16,13), dim3(32,8)>>>(in_w, qw, kw, vw, ow, w16t);
    cvt_x16<<<BNROWS*IND/(256*8), 256>>>(x, x16);
    cvt_e16<<<(int)(((size_t)Bsz*Nn*Nn*Ee)/(256*8)), 256>>>(edges, e16);

    dim3 gg(BNROWS/128, Dd/64);            // (32, 8)
    dim3 gq(BNROWS/128, Dd/64, 3);
    dim3 ag(Hh, Nn/128, Bsz);              // (8, 8, 4)

    gemm_in<<<gg, 256, GEMM_SMEM>>>(x16, w16t, in_b, h, h16, IND);

    for (int l = 0; l < Ll; l++) {
        gemm_qkv<<<gq, 256, GEMM_SMEM>>>(h16, w16t, qb + l*Dd, kb + l*Dd, vb + l*Dd,
                                         q16, k16, v16, l);
        attn16<<<ag, 256, ATTN_SMEM>>>(q16, k16, v16, e16,
                                       ew + l*Ee*Hh, eb + l*Hh, ao16);
        gemm_o<<<gg, 256, GEMM_SMEM>>>(ao16, w16t + WOFF_L(l,3), ob + l*Dd,
                                       h, h, h16);
    }

    ln_kernel<<<BNROWS, 128>>>(h, ln_g, ln_b, out);
}